// round 13
// baseline (speedup 1.0000x reference)
#include <cuda_runtime.h>
#include <cuda_fp16.h>
#include <stdint.h>
#include <math.h>

// ---------------------------------------------------------------------------
// GCLSTM (K=1 ChebConv -> edge data unused). fp16 HMMA path, 2-chunk overlap:
//   pack -> GEMM1(ch0) -> [s2: gates(ch0)+GEMM2(ch0)] || GEMM1(ch1)
//        -> gates(ch1) -> GEMM2(ch1) -> join
// GEMM: BM=128, BN=256, BK=32, 8 warps (2m x 4n), warp 64x64, 4-stage.
// GEMM1 converts fp32 [x|h] -> fp16 in-loader (no prep pass).
// Output tuple: [out | h0 | c0], each 50000*256 fp32.
// ---------------------------------------------------------------------------

#define NNODES 50000
#define CH0    25088           // 196 blocks of 128
#define CH1    (NNODES - CH0)  // 24912 -> 195 blocks

__device__ __half g_P[(size_t)NNODES * 1024];
__device__ __half g_R[(size_t)NNODES * 256];
__device__ __half g_Wt[1024 * 512];
__device__ __half g_WlT[256 * 256];
__device__ float  g_bias[1024];

// ---------------------------------------------------------------------------
__device__ __forceinline__ uint32_t smem_u32(const void* p) {
    uint32_t a;
    asm("{ .reg .u64 t; cvta.to.shared.u64 t, %1; cvt.u32.u64 %0, t; }"
        : "=r"(a) : "l"(p));
    return a;
}
__device__ __forceinline__ void ldm4(uint32_t* a, uint32_t addr) {
    asm volatile("ldmatrix.sync.aligned.m8n8.x4.shared.b16 {%0,%1,%2,%3}, [%4];"
        : "=r"(a[0]), "=r"(a[1]), "=r"(a[2]), "=r"(a[3]) : "r"(addr));
}
__device__ __forceinline__ void mma16816(float* d, const uint32_t* a, const uint32_t* b) {
    asm volatile(
        "mma.sync.aligned.m16n8k16.row.col.f32.f16.f16.f32 "
        "{%0,%1,%2,%3},{%4,%5,%6,%7},{%8,%9},{%0,%1,%2,%3};"
        : "+f"(d[0]), "+f"(d[1]), "+f"(d[2]), "+f"(d[3])
        : "r"(a[0]), "r"(a[1]), "r"(a[2]), "r"(a[3]), "r"(b[0]), "r"(b[1]));
}
__device__ __forceinline__ void cp16(uint32_t dst, const void* src) {
    asm volatile("cp.async.cg.shared.global [%0], [%1], 16;" :: "r"(dst), "l"(src));
}
__device__ __forceinline__ void cp_commit() { asm volatile("cp.async.commit_group;"); }
template <int N>
__device__ __forceinline__ void cp_wait() {
    asm volatile("cp.async.wait_group %0;" :: "n"(N));
}

__device__ __forceinline__ float sigf(float x)  { return 1.f / (1.f + __expf(-x)); }
__device__ __forceinline__ float tanf_(float x) { return 2.f / (1.f + __expf(-2.f * x)) - 1.f; }

// ---------------------------------------------------------------------------
// HMMA GEMM: BM=128, BN=256, BK=32, 8 warps (2m x 4n), warp tile 64x64,
// 4-stage. B via cp.async.
// G1=true : A = [x|h] fp32, LDG->cvt->STS loader; C fp16 (P).
// G1=false: A fp16 via cp.async; C fp32.
// ---------------------------------------------------------------------------
#define ABUF (128 * 80)
#define BBUF (256 * 80)
#define STG  (ABUF + BBUF)
#define SMEM_DYN (4 * STG)           // 122880 B

template <bool G1>
__global__ void __launch_bounds__(256, 1)
hmma_gemm(const float* __restrict__ Ax, const float* __restrict__ Ah,
          const __half* __restrict__ A16, const __half* __restrict__ B,
          void* __restrict__ Cv, const float* __restrict__ bias,
          int M, int Ntot, int K)
{
    extern __shared__ __align__(16) char usm[];
    __shared__ float sbias[256];

    const int tid  = threadIdx.x;
    const int lane = tid & 31;
    const int wid  = tid >> 5;
    const int warpm = wid >> 2;
    const int warpn = wid & 3;
    const int m0 = blockIdx.y * 128;
    const int n0 = blockIdx.x * 256;

    const uint32_t smb = smem_u32(usm);
    sbias[tid] = bias[n0 + tid];

    float acc[4][8][4];
#pragma unroll
    for (int mt = 0; mt < 4; ++mt)
#pragma unroll
        for (int nt = 0; nt < 8; ++nt)
#pragma unroll
            for (int e = 0; e < 4; ++e) acc[mt][nt][e] = 0.f;

    const int nch = K >> 5;

    // ---- A loaders ----
    float4 areg[4];
    const int a_r  = tid >> 3;
    const int a_fq = tid & 7;

    auto fetchA32 = [&](int kc) {
        const float* src = (kc < 8) ? Ax : Ah;
        const int cb = (kc & 7) * 32;
#pragma unroll
        for (int q = 0; q < 4; ++q) {
            int r = a_r + q * 32;
            int gr = m0 + r;
            areg[q] = make_float4(0.f, 0.f, 0.f, 0.f);
            if (gr < M)
                areg[q] = *(const float4*)(src + (size_t)gr * 256 + cb + a_fq * 4);
        }
    };
    auto storeA32 = [&](int st) {
#pragma unroll
        for (int q = 0; q < 4; ++q) {
            int r = a_r + q * 32;
            __half2 h0 = __floats2half2_rn(areg[q].x, areg[q].y);
            __half2 h1 = __floats2half2_rn(areg[q].z, areg[q].w);
            uint2 v;
            v.x = *(uint32_t*)&h0;
            v.y = *(uint32_t*)&h1;
            *(uint2*)(usm + st * STG + r * 80 + a_fq * 8) = v;
        }
    };
    auto issueA16 = [&](int kc, int st) {
#pragma unroll
        for (int q = 0; q < 2; ++q) {
            int u = tid + q * 256;
            int r = u >> 2, kq = u & 3;
            int gr = m0 + r;
            if (gr < M)
                cp16(smb + st * STG + r * 80 + kq * 16,
                     A16 + (size_t)gr * K + kc * 32 + kq * 8);
        }
    };
    auto issueB = [&](int kc, int st) {
        const uint32_t bb = smb + st * STG + ABUF;
#pragma unroll
        for (int q = 0; q < 4; ++q) {
            int u = tid + q * 256;
            int r = u >> 2, kq = u & 3;
            cp16(bb + r * 80 + kq * 16,
                 B + (size_t)(n0 + r) * K + kc * 32 + kq * 8);
        }
    };

    // ---- prologue ----
    if (G1) {
        fetchA32(0); storeA32(0);
        fetchA32(1); storeA32(1);
        fetchA32(2); storeA32(2);
        issueB(0, 0); cp_commit();
        issueB(1, 1); cp_commit();
        issueB(2, 2); cp_commit();
    } else {
        issueA16(0, 0); issueB(0, 0); cp_commit();
        issueA16(1, 1); issueB(1, 1); cp_commit();
        issueA16(2, 2); issueB(2, 2); cp_commit();
    }
    cp_wait<2>();
    __syncthreads();

    const int arow = warpm * 64 + (lane & 15);
    const int aoff = (lane >> 4) * 8;
    const int brow = warpn * 64 + ((lane >> 4) << 3) + (lane & 7);
    const int boff = ((lane >> 3) & 1) * 8;

    for (int t = 0; t < nch; ++t) {
        const bool pf = (t + 3 < nch);
        if (pf) {
            if (G1) fetchA32(t + 3);
            else    issueA16(t + 3, (t + 3) & 3);
            issueB(t + 3, (t + 3) & 3);
        }
        cp_commit();

        const int st = t & 3;
        const uint32_t ab = smb + st * STG + arow * 80;
        const uint32_t bb = smb + st * STG + ABUF + brow * 80;
#pragma unroll
        for (int ks = 0; ks < 2; ++ks) {
            const int k0 = ks * 16;
            uint32_t afr[4][4], bfr[8][2];
#pragma unroll
            for (int mt = 0; mt < 4; ++mt)
                ldm4(afr[mt], ab + mt * 16 * 80 + (k0 + aoff) * 2);
#pragma unroll
            for (int np = 0; np < 4; ++np) {
                uint32_t f[4];
                ldm4(f, bb + np * 16 * 80 + (k0 + boff) * 2);
                bfr[np * 2][0] = f[0]; bfr[np * 2][1] = f[1];
                bfr[np * 2 + 1][0] = f[2]; bfr[np * 2 + 1][1] = f[3];
            }
#pragma unroll
            for (int mt = 0; mt < 4; ++mt)
#pragma unroll
                for (int nt = 0; nt < 8; ++nt)
                    mma16816(acc[mt][nt], afr[mt], bfr[nt]);
        }

        if (G1 && pf) storeA32((t + 3) & 3);
        cp_wait<2>();
        __syncthreads();
    }

    // ---- epilogue ----
#pragma unroll
    for (int mt = 0; mt < 4; ++mt) {
        int r0 = m0 + warpm * 64 + mt * 16 + (lane >> 2);
        int r1 = r0 + 8;
#pragma unroll
        for (int nt = 0; nt < 8; ++nt) {
            int cl = warpn * 64 + nt * 8 + (lane & 3) * 2;
            int cg = n0 + cl;
            float b0 = sbias[cl], b1 = sbias[cl + 1];
            if (G1) {
                __half* C = (__half*)Cv;
                if (r0 < M)
                    *(__half2*)(C + (size_t)r0 * Ntot + cg) =
                        __floats2half2_rn(acc[mt][nt][0] + b0, acc[mt][nt][1] + b1);
                if (r1 < M)
                    *(__half2*)(C + (size_t)r1 * Ntot + cg) =
                        __floats2half2_rn(acc[mt][nt][2] + b0, acc[mt][nt][3] + b1);
            } else {
                float* C = (float*)Cv;
                if (r0 < M)
                    *(float2*)(C + (size_t)r0 * Ntot + cg) =
                        make_float2(acc[mt][nt][0] + b0, acc[mt][nt][1] + b1);
                if (r1 < M)
                    *(float2*)(C + (size_t)r1 * Ntot + cg) =
                        make_float2(acc[mt][nt][2] + b0, acc[mt][nt][3] + b1);
            }
        }
    }
}

// ---------------------------------------------------------------------------
__global__ void pack_kernel(
    const float* __restrict__ Wi, const float* __restrict__ Wf,
    const float* __restrict__ Wc, const float* __restrict__ Wo,
    const float* __restrict__ Ti, const float* __restrict__ Tf,
    const float* __restrict__ Tc, const float* __restrict__ To,
    const float* __restrict__ bthi, const float* __restrict__ bthf,
    const float* __restrict__ bthc, const float* __restrict__ btho,
    const float* __restrict__ bi, const float* __restrict__ bf,
    const float* __restrict__ bc, const float* __restrict__ bo,
    const float* __restrict__ Wlin)
{
    int idx = blockIdx.x * blockDim.x + threadIdx.x;
    if (idx < 524288) {
        int n = idx >> 9, k = idx & 511;
        int g = n >> 8, jj = n & 255;
        float v;
        if (k < 256) {
            const float* W = (g == 0) ? Wi : (g == 1) ? Wf : (g == 2) ? Wc : Wo;
            v = W[k * 256 + jj];
        } else {
            const float* T = (g == 0) ? Ti : (g == 1) ? Tf : (g == 2) ? Tc : To;
            v = T[(k - 256) * 256 + jj];
        }
        g_Wt[idx] = __float2half_rn(v);
    } else if (idx < 524288 + 65536) {
        int i2 = idx - 524288;
        int n = i2 >> 8, k = i2 & 255;
        g_WlT[i2] = __float2half_rn(Wlin[k * 256 + n]);
    } else if (idx < 524288 + 65536 + 1024) {
        int j = idx - 524288 - 65536;
        int g = j >> 8, jj = j & 255;
        const float* bth = (g == 0) ? bthi : (g == 1) ? bthf : (g == 2) ? bthc : btho;
        const float* bb  = (g == 0) ? bi   : (g == 1) ? bf   : (g == 2) ? bc   : bo;
        g_bias[j] = bth[jj] + bb[jj];
    }
}

// ---------------------------------------------------------------------------
// Gates over a row range [base, base+rows): 8 cols/thread.
// ---------------------------------------------------------------------------
__global__ void gates_kernel(const float* __restrict__ c_in,
                             const float* __restrict__ wci,
                             const float* __restrict__ wcf,
                             const float* __restrict__ wco,
                             float* __restrict__ h_out,
                             float* __restrict__ c_out,
                             int base, int rows)
{
    int u = blockIdx.x * blockDim.x + threadIdx.x;
    if (u >= rows * 32) return;
    int n = base + (u >> 5);
    int j = (u & 31) << 3;
    const __half* P = g_P + (size_t)n * 1024;

    uint4 vi = *(const uint4*)(P + j);
    uint4 vf = *(const uint4*)(P + 256 + j);
    uint4 vc = *(const uint4*)(P + 512 + j);
    uint4 vo = *(const uint4*)(P + 768 + j);
    float4 c0 = *(const float4*)(c_in + (size_t)n * 256 + j);
    float4 c1 = *(const float4*)(c_in + (size_t)n * 256 + j + 4);
    float4 wi0 = *(const float4*)(wci + j), wi1 = *(const float4*)(wci + j + 4);
    float4 wf0 = *(const float4*)(wcf + j), wf1 = *(const float4*)(wcf + j + 4);
    float4 wo0 = *(const float4*)(wco + j), wo1 = *(const float4*)(wco + j + 4);

    float pi[8], pf[8], pc[8], po[8];
    {
        const uint32_t* a = &vi.x;
        const uint32_t* b = &vf.x;
        const uint32_t* cc = &vc.x;
        const uint32_t* d = &vo.x;
#pragma unroll
        for (int q = 0; q < 4; ++q) {
            float2 t;
            t = __half22float2(*(const __half2*)&a[q]);  pi[2*q] = t.x; pi[2*q+1] = t.y;
            t = __half22float2(*(const __half2*)&b[q]);  pf[2*q] = t.x; pf[2*q+1] = t.y;
            t = __half22float2(*(const __half2*)&cc[q]); pc[2*q] = t.x; pc[2*q+1] = t.y;
            t = __half22float2(*(const __half2*)&d[q]);  po[2*q] = t.x; po[2*q+1] = t.y;
        }
    }
    float cv[8]  = {c0.x, c0.y, c0.z, c0.w, c1.x, c1.y, c1.z, c1.w};
    float wia[8] = {wi0.x, wi0.y, wi0.z, wi0.w, wi1.x, wi1.y, wi1.z, wi1.w};
    float wfa[8] = {wf0.x, wf0.y, wf0.z, wf0.w, wf1.x, wf1.y, wf1.z, wf1.w};
    float woa[8] = {wo0.x, wo0.y, wo0.z, wo0.w, wo1.x, wo1.y, wo1.z, wo1.w};

    float H[8], Cn[8];
#pragma unroll
    for (int e = 0; e < 8; ++e) {
        float I = sigf(pi[e] + wia[e] * cv[e]);
        float F = sigf(pf[e] + wfa[e] * cv[e]);
        float T = tanf_(pc[e]);
        Cn[e] = F * cv[e] + I * T;
        float O = sigf(po[e] + woa[e] * Cn[e]);
        H[e] = O * tanf_(Cn[e]);
    }

    size_t off = (size_t)n * 256 + j;
    *(float4*)(h_out + off)     = make_float4(H[0], H[1], H[2], H[3]);
    *(float4*)(h_out + off + 4) = make_float4(H[4], H[5], H[6], H[7]);
    *(float4*)(c_out + off)     = make_float4(Cn[0], Cn[1], Cn[2], Cn[3]);
    *(float4*)(c_out + off + 4) = make_float4(Cn[4], Cn[5], Cn[6], Cn[7]);

    uint4 rv;
    __half2 r01 = __floats2half2_rn(fmaxf(H[0], 0.f), fmaxf(H[1], 0.f));
    __half2 r23 = __floats2half2_rn(fmaxf(H[2], 0.f), fmaxf(H[3], 0.f));
    __half2 r45 = __floats2half2_rn(fmaxf(H[4], 0.f), fmaxf(H[5], 0.f));
    __half2 r67 = __floats2half2_rn(fmaxf(H[6], 0.f), fmaxf(H[7], 0.f));
    rv.x = *(uint32_t*)&r01; rv.y = *(uint32_t*)&r23;
    rv.z = *(uint32_t*)&r45; rv.w = *(uint32_t*)&r67;
    *(uint4*)(g_R + off) = rv;
}

// ---------------------------------------------------------------------------
extern "C" void kernel_launch(void* const* d_in, const int* in_sizes, int n_in,
                              void* d_out, int out_size)
{
    const float* x    = (const float*)d_in[0];
    // d_in[1] edge_index, d_in[2] edge_weight -> unused (K=1 ChebConv)
    const float* h    = (const float*)d_in[3];
    const float* c    = (const float*)d_in[4];
    const float* Wi   = (const float*)d_in[5];
    const float* Wf   = (const float*)d_in[6];
    const float* Wc   = (const float*)d_in[7];
    const float* Wo   = (const float*)d_in[8];
    const float* Ti   = (const float*)d_in[9];
    const float* Tf   = (const float*)d_in[10];
    const float* Tc   = (const float*)d_in[11];
    const float* To   = (const float*)d_in[12];
    const float* bthi = (const float*)d_in[13];
    const float* bthf = (const float*)d_in[14];
    const float* bthc = (const float*)d_in[15];
    const float* btho = (const float*)d_in[16];
    const float* wci  = (const float*)d_in[17];
    const float* wcf  = (const float*)d_in[18];
    const float* wco  = (const float*)d_in[19];
    const float* bi   = (const float*)d_in[20];
    const float* bf   = (const float*)d_in[21];
    const float* bc   = (const float*)d_in[22];
    const float* bo   = (const float*)d_in[23];
    const float* Wlin = (const float*)d_in[24];
    const float* blin = (const float*)d_in[25];
    float* out = (float*)d_out;

    float *pBias;
    __half *pP, *pWt, *pWlT, *pR;
    cudaGetSymbolAddress((void**)&pBias, g_bias);
    cudaGetSymbolAddress((void**)&pP, g_P);
    cudaGetSymbolAddress((void**)&pWt, g_Wt);
    cudaGetSymbolAddress((void**)&pWlT, g_WlT);
    cudaGetSymbolAddress((void**)&pR, g_R);

    cudaFuncSetAttribute(hmma_gemm<true>,
                         cudaFuncAttributeMaxDynamicSharedMemorySize, SMEM_DYN);
    cudaFuncSetAttribute(hmma_gemm<false>,
                         cudaFuncAttributeMaxDynamicSharedMemorySize, SMEM_DYN);

    // one-time host-side stream/event setup (no device memory)
    static cudaStream_t s2 = nullptr;
    static cudaEvent_t e1, e2;
    if (!s2) {
        cudaStreamCreateWithFlags(&s2, cudaStreamNonBlocking);
        cudaEventCreateWithFlags(&e1, cudaEventDisableTiming);
        cudaEventCreateWithFlags(&e2, cudaEventDisableTiming);
    }

    const size_t elems = (size_t)NNODES * 256;
    float* hout = out + elems;
    float* cout = out + 2 * elems;

    // pack weights/bias
    pack_kernel<<<(524288 + 65536 + 1024 + 255) / 256, 256>>>(
        Wi, Wf, Wc, Wo, Ti, Tf, Tc, To,
        bthi, bthf, bthc, btho, bi, bf, bc, bo, Wlin);

    // GEMM1 chunk 0 (rows [0, CH0))
    hmma_gemm<true><<<dim3(4, CH0 / 128), 256, SMEM_DYN>>>(
        x, h, nullptr, pWt, pP, pBias, CH0, 1024, 512);
    cudaEventRecord(e1, 0);

    // side stream: gates + GEMM2 for chunk 0, overlapping GEMM1 chunk 1
    cudaStreamWaitEvent(s2, e1, 0);
    gates_kernel<<<(CH0 * 32 + 255) / 256, 256, 0, s2>>>(
        c, wci, wcf, wco, hout, cout, 0, CH0);
    hmma_gemm<false><<<dim3(1, CH0 / 128), 256, SMEM_DYN, s2>>>(
        nullptr, nullptr, pR, pWlT, out, blin, CH0, 256, 256);
    cudaEventRecord(e2, s2);

    // default stream: GEMM1 chunk 1 (rows [CH0, NNODES))
    hmma_gemm<true><<<dim3(4, (CH1 + 127) / 128), 256, SMEM_DYN>>>(
        x + (size_t)CH0 * 256, h + (size_t)CH0 * 256, nullptr, pWt,
        pP + (size_t)CH0 * 1024, pBias, CH1, 1024, 512);

    // gates + GEMM2 for chunk 1
    gates_kernel<<<(CH1 * 32 + 255) / 256, 256>>>(
        c, wci, wcf, wco, hout, cout, CH0, CH1);
    hmma_gemm<false><<<dim3(1, (CH1 + 127) / 128), 256, SMEM_DYN>>>(
        nullptr, nullptr, pR + (size_t)CH0 * 256, pWlT,
        out + (size_t)CH0 * 256, blin, CH1, 256, 256);

    // join side stream
    cudaStreamWaitEvent(0, e2, 0);
}

// round 14
// speedup vs baseline: 1.0328x; 1.0328x over previous
#include <cuda_runtime.h>
#include <cuda_fp16.h>
#include <stdint.h>
#include <math.h>

// ---------------------------------------------------------------------------
// GCLSTM (K=1 ChebConv -> edge data unused). fp16 HMMA path.
//   pack(Wt,bias) -> GEMM1 -> gates -> GEMM2      [default stream]
//   pack(WlinT)  || GEMM1                          [side stream]
//   GEMM1: P(fp16) = [x|h](fp32, cvt in-loader) @ Wt^T + bias  (50000x1024x512)
//   gates: h0, c0 (fp32 only; no R scratch)
//   GEMM2: out = relu(h0)(fp32, relu+cvt in-loader) @ WlinT^T + b_lin
// GEMM: BM=128, BN=256, BK=32, 8 warps (2m x 4n), warp 64x64, 4-stage.
// Output tuple: [out | h0 | c0], each 50000*256 fp32.
// ---------------------------------------------------------------------------

#define NNODES 50000

__device__ __half g_P[(size_t)NNODES * 1024];
__device__ __half g_Wt[1024 * 512];
__device__ __half g_WlT[256 * 256];
__device__ float  g_bias[1024];

// ---------------------------------------------------------------------------
__device__ __forceinline__ uint32_t smem_u32(const void* p) {
    uint32_t a;
    asm("{ .reg .u64 t; cvta.to.shared.u64 t, %1; cvt.u32.u64 %0, t; }"
        : "=r"(a) : "l"(p));
    return a;
}
__device__ __forceinline__ void ldm4(uint32_t* a, uint32_t addr) {
    asm volatile("ldmatrix.sync.aligned.m8n8.x4.shared.b16 {%0,%1,%2,%3}, [%4];"
        : "=r"(a[0]), "=r"(a[1]), "=r"(a[2]), "=r"(a[3]) : "r"(addr));
}
__device__ __forceinline__ void mma16816(float* d, const uint32_t* a, const uint32_t* b) {
    asm volatile(
        "mma.sync.aligned.m16n8k16.row.col.f32.f16.f16.f32 "
        "{%0,%1,%2,%3},{%4,%5,%6,%7},{%8,%9},{%0,%1,%2,%3};"
        : "+f"(d[0]), "+f"(d[1]), "+f"(d[2]), "+f"(d[3])
        : "r"(a[0]), "r"(a[1]), "r"(a[2]), "r"(a[3]), "r"(b[0]), "r"(b[1]));
}
__device__ __forceinline__ void cp16(uint32_t dst, const void* src) {
    asm volatile("cp.async.cg.shared.global [%0], [%1], 16;" :: "r"(dst), "l"(src));
}
__device__ __forceinline__ void cp_commit() { asm volatile("cp.async.commit_group;"); }
template <int N>
__device__ __forceinline__ void cp_wait() {
    asm volatile("cp.async.wait_group %0;" :: "n"(N));
}

__device__ __forceinline__ float sigf(float x)  { return 1.f / (1.f + __expf(-x)); }
__device__ __forceinline__ float tanf_(float x) { return 2.f / (1.f + __expf(-2.f * x)) - 1.f; }

// ---------------------------------------------------------------------------
// HMMA GEMM: BM=128, BN=256, BK=32, 8 warps (2m x 4n), warp tile 64x64,
// 4-stage. A = fp32 (two 256-col sources), converted (+optional relu) in the
// loader. B fp16 [Ntot,K] via cp.async. C = A @ B^T + bias.
// HALF_OUT: C fp16 (GEMM1/P). RELU: apply relu during A conversion (GEMM2).
// ---------------------------------------------------------------------------
#define ABUF (128 * 80)
#define BBUF (256 * 80)
#define STG  (ABUF + BBUF)
#define SMEM_DYN (4 * STG)           // 122880 B

template <bool HALF_OUT, bool RELU>
__global__ void __launch_bounds__(256, 1)
hmma_gemm(const float* __restrict__ Ax, const float* __restrict__ Ah,
          const __half* __restrict__ B,
          void* __restrict__ Cv, const float* __restrict__ bias,
          int M, int Ntot, int K)
{
    extern __shared__ __align__(16) char usm[];
    __shared__ float sbias[256];

    const int tid  = threadIdx.x;
    const int lane = tid & 31;
    const int wid  = tid >> 5;
    const int warpm = wid >> 2;
    const int warpn = wid & 3;
    const int m0 = blockIdx.y * 128;
    const int n0 = blockIdx.x * 256;

    const uint32_t smb = smem_u32(usm);
    sbias[tid] = bias[n0 + tid];

    float acc[4][8][4];
#pragma unroll
    for (int mt = 0; mt < 4; ++mt)
#pragma unroll
        for (int nt = 0; nt < 8; ++nt)
#pragma unroll
            for (int e = 0; e < 4; ++e) acc[mt][nt][e] = 0.f;

    const int nch = K >> 5;

    // ---- A loader: LDG fp32 -> (relu) -> cvt fp16 -> STS ----
    float4 areg[4];
    const int a_r  = tid >> 3;
    const int a_fq = tid & 7;

    auto fetchA32 = [&](int kc) {
        const float* src = (kc < 8) ? Ax : Ah;
        const int cb = (kc & 7) * 32;
#pragma unroll
        for (int q = 0; q < 4; ++q) {
            int r = a_r + q * 32;
            int gr = m0 + r;
            areg[q] = make_float4(0.f, 0.f, 0.f, 0.f);
            if (gr < M)
                areg[q] = *(const float4*)(src + (size_t)gr * 256 + cb + a_fq * 4);
        }
    };
    auto storeA32 = [&](int st) {
#pragma unroll
        for (int q = 0; q < 4; ++q) {
            int r = a_r + q * 32;
            float ax = areg[q].x, ay = areg[q].y, az = areg[q].z, aw = areg[q].w;
            if (RELU) {
                ax = fmaxf(ax, 0.f); ay = fmaxf(ay, 0.f);
                az = fmaxf(az, 0.f); aw = fmaxf(aw, 0.f);
            }
            __half2 h0 = __floats2half2_rn(ax, ay);
            __half2 h1 = __floats2half2_rn(az, aw);
            uint2 v;
            v.x = *(uint32_t*)&h0;
            v.y = *(uint32_t*)&h1;
            *(uint2*)(usm + st * STG + r * 80 + a_fq * 8) = v;
        }
    };
    auto issueB = [&](int kc, int st) {
        const uint32_t bb = smb + st * STG + ABUF;
#pragma unroll
        for (int q = 0; q < 4; ++q) {
            int u = tid + q * 256;
            int r = u >> 2, kq = u & 3;
            cp16(bb + r * 80 + kq * 16,
                 B + (size_t)(n0 + r) * K + kc * 32 + kq * 8);
        }
    };

    // ---- prologue ----
    fetchA32(0); storeA32(0);
    fetchA32(1); storeA32(1);
    fetchA32(2); storeA32(2);
    issueB(0, 0); cp_commit();
    issueB(1, 1); cp_commit();
    issueB(2, 2); cp_commit();
    cp_wait<2>();
    __syncthreads();

    const int arow = warpm * 64 + (lane & 15);
    const int aoff = (lane >> 4) * 8;
    const int brow = warpn * 64 + ((lane >> 4) << 3) + (lane & 7);
    const int boff = ((lane >> 3) & 1) * 8;

    for (int t = 0; t < nch; ++t) {
        const bool pf = (t + 3 < nch);
        if (pf) {
            fetchA32(t + 3);
            issueB(t + 3, (t + 3) & 3);
        }
        cp_commit();

        const int st = t & 3;
        const uint32_t ab = smb + st * STG + arow * 80;
        const uint32_t bb = smb + st * STG + ABUF + brow * 80;
#pragma unroll
        for (int ks = 0; ks < 2; ++ks) {
            const int k0 = ks * 16;
            uint32_t afr[4][4], bfr[8][2];
#pragma unroll
            for (int mt = 0; mt < 4; ++mt)
                ldm4(afr[mt], ab + mt * 16 * 80 + (k0 + aoff) * 2);
#pragma unroll
            for (int np = 0; np < 4; ++np) {
                uint32_t f[4];
                ldm4(f, bb + np * 16 * 80 + (k0 + boff) * 2);
                bfr[np * 2][0] = f[0]; bfr[np * 2][1] = f[1];
                bfr[np * 2 + 1][0] = f[2]; bfr[np * 2 + 1][1] = f[3];
            }
#pragma unroll
            for (int mt = 0; mt < 4; ++mt)
#pragma unroll
                for (int nt = 0; nt < 8; ++nt)
                    mma16816(acc[mt][nt], afr[mt], bfr[nt]);
        }

        if (pf) storeA32((t + 3) & 3);
        cp_wait<2>();
        __syncthreads();
    }

    // ---- epilogue ----
#pragma unroll
    for (int mt = 0; mt < 4; ++mt) {
        int r0 = m0 + warpm * 64 + mt * 16 + (lane >> 2);
        int r1 = r0 + 8;
#pragma unroll
        for (int nt = 0; nt < 8; ++nt) {
            int cl = warpn * 64 + nt * 8 + (lane & 3) * 2;
            int cg = n0 + cl;
            float b0 = sbias[cl], b1 = sbias[cl + 1];
            if (HALF_OUT) {
                __half* C = (__half*)Cv;
                if (r0 < M)
                    *(__half2*)(C + (size_t)r0 * Ntot + cg) =
                        __floats2half2_rn(acc[mt][nt][0] + b0, acc[mt][nt][1] + b1);
                if (r1 < M)
                    *(__half2*)(C + (size_t)r1 * Ntot + cg) =
                        __floats2half2_rn(acc[mt][nt][2] + b0, acc[mt][nt][3] + b1);
            } else {
                float* C = (float*)Cv;
                if (r0 < M)
                    *(float2*)(C + (size_t)r0 * Ntot + cg) =
                        make_float2(acc[mt][nt][0] + b0, acc[mt][nt][1] + b1);
                if (r1 < M)
                    *(float2*)(C + (size_t)r1 * Ntot + cg) =
                        make_float2(acc[mt][nt][2] + b0, acc[mt][nt][3] + b1);
            }
        }
    }
}

// ---------------------------------------------------------------------------
// pack_main: g_Wt[n][k] = Wall[k][n] fp16, g_bias = bth + b. (needed by GEMM1)
// ---------------------------------------------------------------------------
__global__ void pack_main(
    const float* __restrict__ Wi, const float* __restrict__ Wf,
    const float* __restrict__ Wc, const float* __restrict__ Wo,
    const float* __restrict__ Ti, const float* __restrict__ Tf,
    const float* __restrict__ Tc, const float* __restrict__ To,
    const float* __restrict__ bthi, const float* __restrict__ bthf,
    const float* __restrict__ bthc, const float* __restrict__ btho,
    const float* __restrict__ bi, const float* __restrict__ bf,
    const float* __restrict__ bc, const float* __restrict__ bo)
{
    int idx = blockIdx.x * blockDim.x + threadIdx.x;
    if (idx < 524288) {
        int n = idx >> 9, k = idx & 511;
        int g = n >> 8, jj = n & 255;
        float v;
        if (k < 256) {
            const float* W = (g == 0) ? Wi : (g == 1) ? Wf : (g == 2) ? Wc : Wo;
            v = W[k * 256 + jj];
        } else {
            const float* T = (g == 0) ? Ti : (g == 1) ? Tf : (g == 2) ? Tc : To;
            v = T[(k - 256) * 256 + jj];
        }
        g_Wt[idx] = __float2half_rn(v);
    } else if (idx < 524288 + 1024) {
        int j = idx - 524288;
        int g = j >> 8, jj = j & 255;
        const float* bth = (g == 0) ? bthi : (g == 1) ? bthf : (g == 2) ? bthc : btho;
        const float* bb  = (g == 0) ? bi   : (g == 1) ? bf   : (g == 2) ? bc   : bo;
        g_bias[j] = bth[jj] + bb[jj];
    }
}

// pack_wlin: g_WlT[n][k] = Wlin[k][n] fp16. (needed only by GEMM2; runs on s2)
__global__ void pack_wlin(const float* __restrict__ Wlin)
{
    int idx = blockIdx.x * blockDim.x + threadIdx.x;
    if (idx < 65536) {
        int n = idx >> 8, k = idx & 255;
        g_WlT[idx] = __float2half_rn(Wlin[k * 256 + n]);
    }
}

// ---------------------------------------------------------------------------
// Gates from fp16 P: h0, c0 (fp32). 8 cols/thread. (No R scratch.)
// ---------------------------------------------------------------------------
__global__ void gates_kernel(const float* __restrict__ c_in,
                             const float* __restrict__ wci,
                             const float* __restrict__ wcf,
                             const float* __restrict__ wco,
                             float* __restrict__ h_out,
                             float* __restrict__ c_out)
{
    int u = blockIdx.x * blockDim.x + threadIdx.x;   // NNODES*32
    if (u >= NNODES * 32) return;
    int n = u >> 5;
    int j = (u & 31) << 3;
    const __half* P = g_P + (size_t)n * 1024;

    uint4 vi = *(const uint4*)(P + j);
    uint4 vf = *(const uint4*)(P + 256 + j);
    uint4 vc = *(const uint4*)(P + 512 + j);
    uint4 vo = *(const uint4*)(P + 768 + j);
    float4 c0 = *(const float4*)(c_in + (size_t)n * 256 + j);
    float4 c1 = *(const float4*)(c_in + (size_t)n * 256 + j + 4);
    float4 wi0 = *(const float4*)(wci + j), wi1 = *(const float4*)(wci + j + 4);
    float4 wf0 = *(const float4*)(wcf + j), wf1 = *(const float4*)(wcf + j + 4);
    float4 wo0 = *(const float4*)(wco + j), wo1 = *(const float4*)(wco + j + 4);

    float pi[8], pf[8], pc[8], po[8];
    {
        const uint32_t* a = &vi.x;
        const uint32_t* b = &vf.x;
        const uint32_t* cc = &vc.x;
        const uint32_t* d = &vo.x;
#pragma unroll
        for (int q = 0; q < 4; ++q) {
            float2 t;
            t = __half22float2(*(const __half2*)&a[q]);  pi[2*q] = t.x; pi[2*q+1] = t.y;
            t = __half22float2(*(const __half2*)&b[q]);  pf[2*q] = t.x; pf[2*q+1] = t.y;
            t = __half22float2(*(const __half2*)&cc[q]); pc[2*q] = t.x; pc[2*q+1] = t.y;
            t = __half22float2(*(const __half2*)&d[q]);  po[2*q] = t.x; po[2*q+1] = t.y;
        }
    }
    float cv[8]  = {c0.x, c0.y, c0.z, c0.w, c1.x, c1.y, c1.z, c1.w};
    float wia[8] = {wi0.x, wi0.y, wi0.z, wi0.w, wi1.x, wi1.y, wi1.z, wi1.w};
    float wfa[8] = {wf0.x, wf0.y, wf0.z, wf0.w, wf1.x, wf1.y, wf1.z, wf1.w};
    float woa[8] = {wo0.x, wo0.y, wo0.z, wo0.w, wo1.x, wo1.y, wo1.z, wo1.w};

    float H[8], Cn[8];
#pragma unroll
    for (int e = 0; e < 8; ++e) {
        float I = sigf(pi[e] + wia[e] * cv[e]);
        float F = sigf(pf[e] + wfa[e] * cv[e]);
        float T = tanf_(pc[e]);
        Cn[e] = F * cv[e] + I * T;
        float O = sigf(po[e] + woa[e] * Cn[e]);
        H[e] = O * tanf_(Cn[e]);
    }

    size_t off = (size_t)n * 256 + j;
    *(float4*)(h_out + off)     = make_float4(H[0], H[1], H[2], H[3]);
    *(float4*)(h_out + off + 4) = make_float4(H[4], H[5], H[6], H[7]);
    *(float4*)(c_out + off)     = make_float4(Cn[0], Cn[1], Cn[2], Cn[3]);
    *(float4*)(c_out + off + 4) = make_float4(Cn[4], Cn[5], Cn[6], Cn[7]);
}

// ---------------------------------------------------------------------------
extern "C" void kernel_launch(void* const* d_in, const int* in_sizes, int n_in,
                              void* d_out, int out_size)
{
    const float* x    = (const float*)d_in[0];
    // d_in[1] edge_index, d_in[2] edge_weight -> unused (K=1 ChebConv)
    const float* h    = (const float*)d_in[3];
    const float* c    = (const float*)d_in[4];
    const float* Wi   = (const float*)d_in[5];
    const float* Wf   = (const float*)d_in[6];
    const float* Wc   = (const float*)d_in[7];
    const float* Wo   = (const float*)d_in[8];
    const float* Ti   = (const float*)d_in[9];
    const float* Tf   = (const float*)d_in[10];
    const float* Tc   = (const float*)d_in[11];
    const float* To   = (const float*)d_in[12];
    const float* bthi = (const float*)d_in[13];
    const float* bthf = (const float*)d_in[14];
    const float* bthc = (const float*)d_in[15];
    const float* btho = (const float*)d_in[16];
    const float* wci  = (const float*)d_in[17];
    const float* wcf  = (const float*)d_in[18];
    const float* wco  = (const float*)d_in[19];
    const float* bi   = (const float*)d_in[20];
    const float* bf   = (const float*)d_in[21];
    const float* bc   = (const float*)d_in[22];
    const float* bo   = (const float*)d_in[23];
    const float* Wlin = (const float*)d_in[24];
    const float* blin = (const float*)d_in[25];
    float* out = (float*)d_out;

    float *pBias;
    __half *pP, *pWt, *pWlT;
    cudaGetSymbolAddress((void**)&pBias, g_bias);
    cudaGetSymbolAddress((void**)&pP, g_P);
    cudaGetSymbolAddress((void**)&pWt, g_Wt);
    cudaGetSymbolAddress((void**)&pWlT, g_WlT);

    cudaFuncSetAttribute((const void*)hmma_gemm<true, false>,
                         cudaFuncAttributeMaxDynamicSharedMemorySize, SMEM_DYN);
    cudaFuncSetAttribute((const void*)hmma_gemm<false, true>,
                         cudaFuncAttributeMaxDynamicSharedMemorySize, SMEM_DYN);

    // one-time host-side stream/event setup (no device memory)
    static cudaStream_t s2 = nullptr;
    static cudaEvent_t evFork, evWlin;
    if (!s2) {
        cudaStreamCreateWithFlags(&s2, cudaStreamNonBlocking);
        cudaEventCreateWithFlags(&evFork, cudaEventDisableTiming);
        cudaEventCreateWithFlags(&evWlin, cudaEventDisableTiming);
    }

    const size_t elems = (size_t)NNODES * 256;
    float* hout = out + elems;
    float* cout = out + 2 * elems;

    // pack Wt+bias (default; GEMM1 depends on it)
    pack_main<<<(524288 + 1024 + 255) / 256, 256>>>(
        Wi, Wf, Wc, Wo, Ti, Tf, Tc, To,
        bthi, bthf, bthc, btho, bi, bf, bc, bo);

    // pack WlinT on side stream (overlaps GEMM1; only GEMM2 needs it)
    cudaEventRecord(evFork, 0);
    cudaStreamWaitEvent(s2, evFork, 0);
    pack_wlin<<<65536 / 256, 256, 0, s2>>>(Wlin);
    cudaEventRecord(evWlin, s2);

    // GEMM1: P = [x|h] @ Wt^T + bias (A converted in-loader)
    hmma_gemm<true, false><<<dim3(4, (NNODES + 127) / 128), 256, SMEM_DYN>>>(
        x, h, pWt, pP, pBias, NNODES, 1024, 512);

    // gates -> h0, c0 (fp32 only)
    gates_kernel<<<(NNODES * 32 + 255) / 256, 256>>>(
        c, wci, wcf, wco, hout, cout);

    // GEMM2: out = relu(h0) @ WlinT^T + b_lin (relu+cvt in-loader)
    cudaStreamWaitEvent(0, evWlin, 0);
    hmma_gemm<false, true><<<dim3(1, (NNODES + 127) / 128), 256, SMEM_DYN>>>(
        hout, hout, pWlT, out, blin, NNODES, 256, 256);
}